// round 7
// baseline (speedup 1.0000x reference)
#include <cuda_runtime.h>
#include <cuda_fp16.h>

#define NMAX 100000
#define D 64
#define CAP 64             // per-row bucket capacity (Poisson(16): P(deg>=64)*N ~ 1e-20)
#define FULL 0xffffffffu

typedef unsigned long long u64;

// Scratch (no device allocation). __device__ globals are zero-initialized.
__device__ __half g_hid[NMAX * D];            // 12.8 MB (fp16 hidden)
__device__ int    g_cnt[NMAX];                // degree counters; reset by SpmmC each call
__device__ int2   g_edge[(size_t)NMAX * CAP]; // 51.2 MB row buckets: (col, val-bits)

__device__ __forceinline__ float wsum(float v) {
#pragma unroll
    for (int o = 16; o; o >>= 1) v += __shfl_xor_sync(FULL, v, o);
    return v;
}

// fast artanh for x in [0, 1): 0.5*ln((1+x)/(1-x)); ~1e-6 rel err
__device__ __forceinline__ float artanh_f(float x) {
    x = fminf(x, 1.0f - 1e-7f);
    return 0.5f * __logf(__fdividef(1.0f + x, 1.0f - x));
}

__device__ __forceinline__ u64 ffma2(u64 a, u64 b, u64 c) {
    u64 d;
    asm("fma.rn.f32x2 %0, %1, %2, %3;" : "=l"(d) : "l"(a), "l"(b), "l"(c));
    return d;
}
__device__ __forceinline__ float2 unpack2(u64 v) {
    float2 r;
    asm("mov.b64 {%0, %1}, %2;" : "=f"(r.x), "=f"(r.y) : "l"(v));
    return r;
}
__device__ __forceinline__ u64 pack2(float lo, float hi) {
    u64 v;
    asm("mov.b64 %0, {%1, %2};" : "=l"(v) : "f"(lo), "f"(hi));
    return v;
}

// ---------------------------------------------------------------------------
// Kernel AF: blocks [0, NA) run the fused linear+mobius+logmap0 (-> g_hid fp16);
//            blocks [NA, ...) bucket edges by destination row (g_edge/g_cnt).
// ---------------------------------------------------------------------------
__global__ void __launch_bounds__(256) kernelAF(
    const float* __restrict__ x, const float* __restrict__ W,
    const float* __restrict__ ev, const int* __restrict__ rows,
    const int* __restrict__ cols, int N, int E, int NA)
{
    if ((int)blockIdx.x >= NA) {
        // ---- Fill path: 8 edges per thread, independent (MLP=8) ----
        int e0 = (blockIdx.x - NA) * 2048 + threadIdx.x;
#pragma unroll
        for (int u = 0; u < 8; u++) {
            int e = e0 + u * 256;
            if (e < E) {
                int r = __ldg(&rows[e]);
                int pos = atomicAdd(&g_cnt[r], 1);
                if (pos < CAP)
                    g_edge[(size_t)r * CAP + pos] =
                        make_int2(__ldg(&cols[e]), __float_as_int(__ldg(&ev[e])));
            }
        }
        return;
    }

    // ---- A path: warp handles 8 rows as 4 packed row-pairs ----
    __shared__ float  Ws[D * 65];     // W^T, padded
    __shared__ float2 Xp[8][D][4];    // packed x row-pairs

    const int tid  = threadIdx.x;
    const int warp = tid >> 5;
    const int lane = tid & 31;

    for (int i = tid; i < D * D; i += 256) {
        int d = i >> 6, k = i & 63;
        Ws[k * 65 + d] = W[i];
    }

    const int base = (blockIdx.x * 8 + warp) * 8;
#pragma unroll
    for (int p = 0; p < 4; p++) {
        int r0 = base + 2 * p, r1 = r0 + 1;
        float a0 = (r0 < N) ? x[r0 * D + lane]      : 0.f;
        float a1 = (r0 < N) ? x[r0 * D + lane + 32] : 0.f;
        float b0 = (r1 < N) ? x[r1 * D + lane]      : 0.f;
        float b1 = (r1 < N) ? x[r1 * D + lane + 32] : 0.f;
        Xp[warp][lane][p]      = make_float2(a0, b0);
        Xp[warp][lane + 32][p] = make_float2(a1, b1);
    }
    __syncthreads();
    if (base >= N) return;

    u64 acc[4][2];
#pragma unroll
    for (int p = 0; p < 4; p++) { acc[p][0] = 0ull; acc[p][1] = 0ull; }

#pragma unroll 16
    for (int k = 0; k < D; k++) {
        float w0f = Ws[k * 65 + lane];
        float w1f = Ws[k * 65 + lane + 32];
        u64 w0 = pack2(w0f, w0f);
        u64 w1 = pack2(w1f, w1f);
        const u64* xr = reinterpret_cast<const u64*>(&Xp[warp][k][0]);
#pragma unroll
        for (int p = 0; p < 4; p++) {
            u64 xp = xr[p];
            acc[p][0] = ffma2(w0, xp, acc[p][0]);
            acc[p][1] = ffma2(w1, xp, acc[p][1]);
        }
    }

#pragma unroll
    for (int p = 0; p < 4; p++) {
        float2 c0 = unpack2(acc[p][0]);
        float2 c1 = unpack2(acc[p][1]);
#pragma unroll
        for (int q = 0; q < 2; q++) {
            int row = base + 2 * p + q;
            if (row < N) {                 // uniform across warp
                float a0 = q ? c0.y : c0.x;
                float a1 = q ? c1.y : c1.x;
                float x0 = x[row * D + lane];        // L1 hits
                float x1 = x[row * D + lane + 32];
                float xn  = fmaxf(sqrtf(wsum(x0 * x0 + x1 * x1)), 1e-15f);
                float mxn = fmaxf(sqrtf(wsum(a0 * a0 + a1 * a1)), 1e-15f);
                unsigned bz = __ballot_sync(FULL, (a0 == 0.f) && (a1 == 0.f));
                float t = tanhf(__fdividef(mxn, xn) * artanh_f(xn));
                float scale = __fdividef(t, mxn);
                if (bz == FULL) scale = 0.f;
                float pn = fmaxf(t, 1e-15f);
                float hs = __fdividef(artanh_f(pn), pn) * scale;
                g_hid[row * D + lane]      = __float2half_rn(a0 * hs);
                g_hid[row * D + lane + 32] = __float2half_rn(a1 * hs);
            }
        }
    }
}

// ---------------------------------------------------------------------------
// Fused SpMM (fp16 gather, fp32 accumulate) + expmap0 -> relu(logmap0)
// -> expmap0 -> proj => out.  One warp per row; lane owns feature-pair
// (2*lane, 2*lane+1).  Edge records read at uniform address (L1 broadcast).
// Gathers batched 8-wide into registers to force MLP=8.
// __launch_bounds__(256, 4): reg ceiling 64 so ptxas keeps 8 loads in flight.
// ---------------------------------------------------------------------------
__global__ void __launch_bounds__(256, 4) kernelSpmmC(float* __restrict__ out, int N)
{
    int row = blockIdx.x * 8 + (threadIdx.x >> 5);
    if (row >= N) return;
    int lane = threadIdx.x & 31;
    int deg = min(g_cnt[row], CAP);
    if (lane == 0) g_cnt[row] = 0;          // restore invariant for next call
    const int2* eb = &g_edge[(size_t)row * CAP];
    const __half2* hp = reinterpret_cast<const __half2*>(g_hid);

    float acc0 = 0.f, acc1 = 0.f;
    int j = 0;
    for (; j + 8 <= deg; j += 8) {
        float   vv[8];
        __half2 hv[8];
#pragma unroll
        for (int u = 0; u < 8; u++) {       // phase 1: issue 8 independent gathers
            int2 er = __ldg(&eb[j + u]);    // uniform address -> L1 broadcast
            vv[u] = __int_as_float(er.y);
            hv[u] = __ldg(&hp[(size_t)er.x * 32 + lane]);
        }
#pragma unroll
        for (int u = 0; u < 8; u++) {       // phase 2: consume
            float2 hf = __half22float2(hv[u]);
            acc0 = fmaf(vv[u], hf.x, acc0);
            acc1 = fmaf(vv[u], hf.y, acc1);
        }
    }
    if (j + 4 <= deg) {
        float   vv[4];
        __half2 hv[4];
#pragma unroll
        for (int u = 0; u < 4; u++) {
            int2 er = __ldg(&eb[j + u]);
            vv[u] = __int_as_float(er.y);
            hv[u] = __ldg(&hp[(size_t)er.x * 32 + lane]);
        }
#pragma unroll
        for (int u = 0; u < 4; u++) {
            float2 hf = __half22float2(hv[u]);
            acc0 = fmaf(vv[u], hf.x, acc0);
            acc1 = fmaf(vv[u], hf.y, acc1);
        }
        j += 4;
    }
    for (; j < deg; j++) {
        int2 er = __ldg(&eb[j]);
        float v = __int_as_float(er.y);
        float2 hf = __half22float2(__ldg(&hp[(size_t)er.x * 32 + lane]));
        acc0 = fmaf(v, hf.x, acc0);
        acc1 = fmaf(v, hf.y, acc1);
    }

    // expmap0: |p| = tanh(un) analytically
    float un = fmaxf(sqrtf(wsum(acc0 * acc0 + acc1 * acc1)), 1e-15f);
    float tn = tanhf(un);
    float ps = __fdividef(tn, un);
    float pn = fmaxf(tn, 1e-15f);
    // relu(logmap0(p))
    float as = __fdividef(artanh_f(pn), pn) * ps;
    float xt0 = fmaxf(as * acc0, 0.f), xt1 = fmaxf(as * acc1, 0.f);
    // expmap0; |out| = tanh(xn)
    float xn = fmaxf(sqrtf(wsum(xt0 * xt0 + xt1 * xt1)), 1e-15f);
    float txn = tanhf(xn);
    float os = __fdividef(txn, xn);
    float o0 = os * xt0, o1 = os * xt1;
    // proj
    float on = fmaxf(txn, 1e-15f);
    float mxn = 1.0f - 1e-5f;
    if (on > mxn) { float f = __fdividef(mxn, on); o0 *= f; o1 *= f; }
    reinterpret_cast<float2*>(out)[row * 32 + lane] = make_float2(o0, o1);
}

// ---------------------------------------------------------------------------
extern "C" void kernel_launch(void* const* d_in, const int* in_sizes, int n_in,
                              void* d_out, int out_size)
{
    const float* x    = (const float*)d_in[0];
    const float* W    = (const float*)d_in[1];
    const float* ev   = (const float*)d_in[2];
    const int*   rows = (const int*)d_in[3];
    const int*   cols = (const int*)d_in[4];
    float* out = (float*)d_out;

    int N = in_sizes[0] / D;
    int E = in_sizes[2];

    int NA = (N + 63) / 64;           // A blocks (8 rows/warp * 8 warps)
    int NF = (E + 2047) / 2048;       // Fill blocks (8 edges/thread)
    kernelAF<<<NA + NF, 256>>>(x, W, ev, rows, cols, N, E, NA);
    kernelSpmmC<<<(N + 7) / 8, 256>>>(out, N);
}

// round 8
// speedup vs baseline: 1.5812x; 1.5812x over previous
#include <cuda_runtime.h>

#define NMAX 100000
#define D 64
#define CAP 128            // per-row bucket capacity (Poisson(16): P(deg>=128) ~ 0)
#define FULL 0xffffffffu

typedef unsigned long long u64;

// Scratch (no device allocation). __device__ globals are zero-initialized,
// and SpmmC resets g_cnt after reading, so every call sees zeros.
__device__ float g_hidden[NMAX * D];          // 25.6 MB
__device__ int   g_cnt[NMAX];
__device__ int2  g_edge[(size_t)NMAX * CAP];  // 102.4 MB: (col, val-bits)

__device__ __forceinline__ float wsum(float v) {
#pragma unroll
    for (int o = 16; o; o >>= 1) v += __shfl_xor_sync(FULL, v, o);
    return v;
}

// fast artanh for x in [0, 1): 0.5*ln((1+x)/(1-x)); ~1e-6 rel err
__device__ __forceinline__ float artanh_f(float x) {
    x = fminf(x, 1.0f - 1e-7f);
    return 0.5f * __logf(__fdividef(1.0f + x, 1.0f - x));
}

__device__ __forceinline__ u64 ffma2(u64 a, u64 b, u64 c) {
    u64 d;
    asm("fma.rn.f32x2 %0, %1, %2, %3;" : "=l"(d) : "l"(a), "l"(b), "l"(c));
    return d;
}
__device__ __forceinline__ float2 unpack2(u64 v) {
    float2 r;
    asm("mov.b64 {%0, %1}, %2;" : "=f"(r.x), "=f"(r.y) : "l"(v));
    return r;
}
__device__ __forceinline__ u64 pack2(float lo, float hi) {
    u64 v;
    asm("mov.b64 %0, {%1, %2};" : "=l"(v) : "f"(lo), "f"(hi));
    return v;
}

// ---------------------------------------------------------------------------
// Kernel AF: blocks [0, NA) run fused linear+mobius+logmap0 (-> g_hidden);
//            blocks [NA, ...) bucket edges by destination row (g_edge/g_cnt).
// Disjoint state; Fill hides under A's compute.
// ---------------------------------------------------------------------------
__global__ void __launch_bounds__(256) kernelAF(
    const float* __restrict__ x, const float* __restrict__ W,
    const float* __restrict__ ev, const int* __restrict__ rows,
    const int* __restrict__ cols, int N, int E, int NA)
{
    if ((int)blockIdx.x >= NA) {
        // ---- Fill path: 8 edges per thread, independent (MLP=8) ----
        int e0 = (blockIdx.x - NA) * 2048 + threadIdx.x;
#pragma unroll
        for (int u = 0; u < 8; u++) {
            int e = e0 + u * 256;
            if (e < E) {
                int r = __ldg(&rows[e]);
                int pos = atomicAdd(&g_cnt[r], 1);
                if (pos < CAP)
                    g_edge[(size_t)r * CAP + pos] =
                        make_int2(__ldg(&cols[e]), __float_as_int(__ldg(&ev[e])));
            }
        }
        return;
    }

    // ---- A path: warp handles 8 rows as 4 packed row-pairs ----
    __shared__ float  Ws[D * 65];     // W^T, padded
    __shared__ float2 Xp[8][D][4];    // packed x row-pairs

    const int tid  = threadIdx.x;
    const int warp = tid >> 5;
    const int lane = tid & 31;

    for (int i = tid; i < D * D; i += 256) {
        int d = i >> 6, k = i & 63;
        Ws[k * 65 + d] = W[i];
    }

    const int base = (blockIdx.x * 8 + warp) * 8;
#pragma unroll
    for (int p = 0; p < 4; p++) {
        int r0 = base + 2 * p, r1 = r0 + 1;
        float a0 = (r0 < N) ? x[r0 * D + lane]      : 0.f;
        float a1 = (r0 < N) ? x[r0 * D + lane + 32] : 0.f;
        float b0 = (r1 < N) ? x[r1 * D + lane]      : 0.f;
        float b1 = (r1 < N) ? x[r1 * D + lane + 32] : 0.f;
        Xp[warp][lane][p]      = make_float2(a0, b0);
        Xp[warp][lane + 32][p] = make_float2(a1, b1);
    }
    __syncthreads();
    if (base >= N) return;

    u64 acc[4][2];
#pragma unroll
    for (int p = 0; p < 4; p++) { acc[p][0] = 0ull; acc[p][1] = 0ull; }

#pragma unroll 16
    for (int k = 0; k < D; k++) {
        float w0f = Ws[k * 65 + lane];
        float w1f = Ws[k * 65 + lane + 32];
        u64 w0 = pack2(w0f, w0f);
        u64 w1 = pack2(w1f, w1f);
        const u64* xr = reinterpret_cast<const u64*>(&Xp[warp][k][0]);
#pragma unroll
        for (int p = 0; p < 4; p++) {
            u64 xp = xr[p];
            acc[p][0] = ffma2(w0, xp, acc[p][0]);
            acc[p][1] = ffma2(w1, xp, acc[p][1]);
        }
    }

#pragma unroll
    for (int p = 0; p < 4; p++) {
        float2 c0 = unpack2(acc[p][0]);   // {mx[r0][lane],    mx[r1][lane]}
        float2 c1 = unpack2(acc[p][1]);   // {mx[r0][lane+32], mx[r1][lane+32]}
#pragma unroll
        for (int q = 0; q < 2; q++) {
            int row = base + 2 * p + q;
            if (row < N) {                 // uniform across warp
                float a0 = q ? c0.y : c0.x;
                float a1 = q ? c1.y : c1.x;
                float x0 = x[row * D + lane];        // L1 hits
                float x1 = x[row * D + lane + 32];
                float xn  = fmaxf(sqrtf(wsum(x0 * x0 + x1 * x1)), 1e-15f);
                float mxn = fmaxf(sqrtf(wsum(a0 * a0 + a1 * a1)), 1e-15f);
                unsigned bz = __ballot_sync(FULL, (a0 == 0.f) && (a1 == 0.f));
                float t = tanhf(__fdividef(mxn, xn) * artanh_f(xn));
                float scale = __fdividef(t, mxn);
                if (bz == FULL) scale = 0.f;
                // |res| = t analytically (res = mx*scale, scale >= 0)
                float pn = fmaxf(t, 1e-15f);
                float hs = __fdividef(artanh_f(pn), pn) * scale;
                g_hidden[row * D + lane]      = a0 * hs;
                g_hidden[row * D + lane + 32] = a1 * hs;
            }
        }
    }
}

// ---------------------------------------------------------------------------
// Fused SpMM (gather) + expmap0 -> relu(logmap0) -> expmap0 -> proj => out
// One warp per row. Lanes cooperatively load 32 edge records (one coalesced
// LDG.64 per 32 edges), broadcast each via register shuffle; after that the
// whole row's gather stream has no load->load dependence (full-row MLP).
// Proven shape from the 123.8us round. Also resets g_cnt for the next call.
// ---------------------------------------------------------------------------
__global__ void __launch_bounds__(256) kernelSpmmC(float* __restrict__ out, int N)
{
    int row = blockIdx.x * 8 + (threadIdx.x >> 5);
    if (row >= N) return;
    int lane = threadIdx.x & 31;
    int deg = min(g_cnt[row], CAP);
    if (lane == 0) g_cnt[row] = 0;          // restore invariant for next call
    const int2* eb = &g_edge[(size_t)row * CAP];

    float acc0 = 0.f, acc1 = 0.f;
    for (int s = 0; s < deg; s += 32) {
        int m = min(32, deg - s);
        u64 ep = 0ull;
        if (lane < m) {
            int2 er = __ldg(&eb[s + lane]);
            ep = pack2(__int_as_float(er.x), __int_as_float(er.y));
        }
        int j = 0;
        for (; j + 4 <= m; j += 4) {
#pragma unroll
            for (int u = 0; u < 4; u++) {
                u64 q = __shfl_sync(FULL, ep, j + u);
                float2 cv = unpack2(q);
                int c = __float_as_int(cv.x);
                const float* h = &g_hidden[(size_t)c * D];
                acc0 = fmaf(cv.y, __ldg(&h[lane]),      acc0);
                acc1 = fmaf(cv.y, __ldg(&h[lane + 32]), acc1);
            }
        }
        for (; j < m; j++) {
            u64 q = __shfl_sync(FULL, ep, j);
            float2 cv = unpack2(q);
            int c = __float_as_int(cv.x);
            const float* h = &g_hidden[(size_t)c * D];
            acc0 = fmaf(cv.y, __ldg(&h[lane]),      acc0);
            acc1 = fmaf(cv.y, __ldg(&h[lane + 32]), acc1);
        }
    }

    // expmap0: |p| = tanh(un) analytically
    float un = fmaxf(sqrtf(wsum(acc0 * acc0 + acc1 * acc1)), 1e-15f);
    float tn = tanhf(un);
    float ps = __fdividef(tn, un);
    float pn = fmaxf(tn, 1e-15f);
    // relu(logmap0(p))
    float as = __fdividef(artanh_f(pn), pn) * ps;
    float xt0 = fmaxf(as * acc0, 0.f), xt1 = fmaxf(as * acc1, 0.f);
    // expmap0; |out| = tanh(xn)
    float xn = fmaxf(sqrtf(wsum(xt0 * xt0 + xt1 * xt1)), 1e-15f);
    float txn = tanhf(xn);
    float os = __fdividef(txn, xn);
    float o0 = os * xt0, o1 = os * xt1;
    // proj
    float on = fmaxf(txn, 1e-15f);
    float mxn = 1.0f - 1e-5f;
    if (on > mxn) { float f = __fdividef(mxn, on); o0 *= f; o1 *= f; }
    out[row * D + lane]      = o0;
    out[row * D + lane + 32] = o1;
}

// ---------------------------------------------------------------------------
extern "C" void kernel_launch(void* const* d_in, const int* in_sizes, int n_in,
                              void* d_out, int out_size)
{
    const float* x    = (const float*)d_in[0];
    const float* W    = (const float*)d_in[1];
    const float* ev   = (const float*)d_in[2];
    const int*   rows = (const int*)d_in[3];
    const int*   cols = (const int*)d_in[4];
    float* out = (float*)d_out;

    int N = in_sizes[0] / D;
    int E = in_sizes[2];

    int NA = (N + 63) / 64;           // A blocks (8 rows/warp * 8 warps)
    int NF = (E + 2047) / 2048;       // Fill blocks (8 edges/thread)
    kernelAF<<<NA + NF, 256>>>(x, W, ev, rows, cols, N, E, NA);
    kernelSpmmC<<<(N + 7) / 8, 256>>>(out, N);
}

// round 9
// speedup vs baseline: 3.4692x; 2.1941x over previous
#include <cuda_runtime.h>

#define NMAX 100000
#define D 64
#define CAP 128            // per-row bucket capacity (Poisson(16): P(deg>=128) ~ 0)
#define FULL 0xffffffffu

typedef unsigned long long u64;

// Scratch (no device allocation).
__device__ float g_hidden[NMAX * D];          // 25.6 MB
__device__ int   g_cnt[NMAX];
__device__ int2  g_edge[(size_t)NMAX * CAP];  // 102.4 MB: (col, val-bits)

__device__ __forceinline__ float wsum(float v) {
#pragma unroll
    for (int o = 16; o; o >>= 1) v += __shfl_xor_sync(FULL, v, o);
    return v;
}

// exact artanh with reference clipping (used in SpmmC, matching the R4 winner)
__device__ __forceinline__ float artanh_c(float x) {
    return atanhf(fminf(x, 1.0f - 1e-7f));
}

// fast artanh for x in [0, 1): 0.5*ln((1+x)/(1-x)); ~1e-6 rel err (A epilogue)
__device__ __forceinline__ float artanh_f(float x) {
    x = fminf(x, 1.0f - 1e-7f);
    return 0.5f * __logf(__fdividef(1.0f + x, 1.0f - x));
}

__device__ __forceinline__ u64 ffma2(u64 a, u64 b, u64 c) {
    u64 d;
    asm("fma.rn.f32x2 %0, %1, %2, %3;" : "=l"(d) : "l"(a), "l"(b), "l"(c));
    return d;
}
__device__ __forceinline__ float2 unpack2(u64 v) {
    float2 r;
    asm("mov.b64 {%0, %1}, %2;" : "=f"(r.x), "=f"(r.y) : "l"(v));
    return r;
}
__device__ __forceinline__ u64 pack2(float lo, float hi) {
    u64 v;
    asm("mov.b64 %0, {%1, %2};" : "=l"(v) : "f"(lo), "f"(hi));
    return v;
}

// ---------------------------------------------------------------------------
// Kernel Z: zero the degree counters (runs before AF each call).
// ---------------------------------------------------------------------------
__global__ void __launch_bounds__(256) kernelZ()
{
    int i = blockIdx.x * 256 + threadIdx.x;
    if (i < NMAX) g_cnt[i] = 0;
}

// ---------------------------------------------------------------------------
// Kernel AF: blocks [0, NA) run fused linear+mobius+logmap0 (-> g_hidden);
//            blocks [NA, ...) bucket edges by destination row (g_edge/g_cnt).
// Disjoint state; Fill hides under A's compute. (Measured ~45us in R8.)
// ---------------------------------------------------------------------------
__global__ void __launch_bounds__(256) kernelAF(
    const float* __restrict__ x, const float* __restrict__ W,
    const float* __restrict__ ev, const int* __restrict__ rows,
    const int* __restrict__ cols, int N, int E, int NA)
{
    if ((int)blockIdx.x >= NA) {
        // ---- Fill path: 8 edges per thread, independent (MLP=8) ----
        int e0 = (blockIdx.x - NA) * 2048 + threadIdx.x;
#pragma unroll
        for (int u = 0; u < 8; u++) {
            int e = e0 + u * 256;
            if (e < E) {
                int r = __ldg(&rows[e]);
                int pos = atomicAdd(&g_cnt[r], 1);
                if (pos < CAP)
                    g_edge[(size_t)r * CAP + pos] =
                        make_int2(__ldg(&cols[e]), __float_as_int(__ldg(&ev[e])));
            }
        }
        return;
    }

    // ---- A path: warp handles 8 rows as 4 packed row-pairs ----
    __shared__ float  Ws[D * 65];     // W^T, padded
    __shared__ float2 Xp[8][D][4];    // packed x row-pairs

    const int tid  = threadIdx.x;
    const int warp = tid >> 5;
    const int lane = tid & 31;

    for (int i = tid; i < D * D; i += 256) {
        int d = i >> 6, k = i & 63;
        Ws[k * 65 + d] = W[i];
    }

    const int base = (blockIdx.x * 8 + warp) * 8;
#pragma unroll
    for (int p = 0; p < 4; p++) {
        int r0 = base + 2 * p, r1 = r0 + 1;
        float a0 = (r0 < N) ? x[r0 * D + lane]      : 0.f;
        float a1 = (r0 < N) ? x[r0 * D + lane + 32] : 0.f;
        float b0 = (r1 < N) ? x[r1 * D + lane]      : 0.f;
        float b1 = (r1 < N) ? x[r1 * D + lane + 32] : 0.f;
        Xp[warp][lane][p]      = make_float2(a0, b0);
        Xp[warp][lane + 32][p] = make_float2(a1, b1);
    }
    __syncthreads();
    if (base >= N) return;

    u64 acc[4][2];
#pragma unroll
    for (int p = 0; p < 4; p++) { acc[p][0] = 0ull; acc[p][1] = 0ull; }

#pragma unroll 16
    for (int k = 0; k < D; k++) {
        float w0f = Ws[k * 65 + lane];
        float w1f = Ws[k * 65 + lane + 32];
        u64 w0 = pack2(w0f, w0f);
        u64 w1 = pack2(w1f, w1f);
        const u64* xr = reinterpret_cast<const u64*>(&Xp[warp][k][0]);
#pragma unroll
        for (int p = 0; p < 4; p++) {
            u64 xp = xr[p];
            acc[p][0] = ffma2(w0, xp, acc[p][0]);
            acc[p][1] = ffma2(w1, xp, acc[p][1]);
        }
    }

#pragma unroll
    for (int p = 0; p < 4; p++) {
        float2 c0 = unpack2(acc[p][0]);   // {mx[r0][lane],    mx[r1][lane]}
        float2 c1 = unpack2(acc[p][1]);   // {mx[r0][lane+32], mx[r1][lane+32]}
#pragma unroll
        for (int q = 0; q < 2; q++) {
            int row = base + 2 * p + q;
            if (row < N) {                 // uniform across warp
                float a0 = q ? c0.y : c0.x;
                float a1 = q ? c1.y : c1.x;
                float x0 = x[row * D + lane];        // L1 hits
                float x1 = x[row * D + lane + 32];
                float xn  = fmaxf(sqrtf(wsum(x0 * x0 + x1 * x1)), 1e-15f);
                float mxn = fmaxf(sqrtf(wsum(a0 * a0 + a1 * a1)), 1e-15f);
                unsigned bz = __ballot_sync(FULL, (a0 == 0.f) && (a1 == 0.f));
                float t = tanhf(__fdividef(mxn, xn) * artanh_f(xn));
                float scale = __fdividef(t, mxn);
                if (bz == FULL) scale = 0.f;
                // |res| = t analytically (res = mx*scale, scale >= 0)
                float pn = fmaxf(t, 1e-15f);
                float hs = __fdividef(artanh_f(pn), pn) * scale;
                g_hidden[row * D + lane]      = a0 * hs;
                g_hidden[row * D + lane + 32] = a1 * hs;
            }
        }
    }
}

// ---------------------------------------------------------------------------
// Fused SpMM (gather) + expmap0 -> relu(logmap0) -> expmap0 -> proj => out
// BYTE-IDENTICAL to the R4 123.8us winner: no stores before the loop,
// cooperative eb load + u64 shuffle broadcast, unroll-4, exact epilogue.
// ---------------------------------------------------------------------------
__global__ void __launch_bounds__(256) kernelSpmmC(float* __restrict__ out, int N)
{
    int row = blockIdx.x * 8 + (threadIdx.x >> 5);
    if (row >= N) return;
    int lane = threadIdx.x & 31;
    int deg = min(g_cnt[row], CAP);
    const int2* eb = &g_edge[(size_t)row * CAP];

    float acc0 = 0.f, acc1 = 0.f;
    for (int s = 0; s < deg; s += 32) {
        int m = min(32, deg - s);
        u64 ep = 0ull;
        if (lane < m) {
            int2 er = __ldg(&eb[s + lane]);
            ep = pack2(__int_as_float(er.x), __int_as_float(er.y));
        }
        int j = 0;
        for (; j + 4 <= m; j += 4) {
#pragma unroll
            for (int u = 0; u < 4; u++) {
                u64 q = __shfl_sync(FULL, ep, j + u);
                float2 cv = unpack2(q);
                int c = __float_as_int(cv.x);
                const float* h = &g_hidden[(size_t)c * D];
                acc0 = fmaf(cv.y, __ldg(&h[lane]),      acc0);
                acc1 = fmaf(cv.y, __ldg(&h[lane + 32]), acc1);
            }
        }
        for (; j < m; j++) {
            u64 q = __shfl_sync(FULL, ep, j);
            float2 cv = unpack2(q);
            int c = __float_as_int(cv.x);
            const float* h = &g_hidden[(size_t)c * D];
            acc0 = fmaf(cv.y, __ldg(&h[lane]),      acc0);
            acc1 = fmaf(cv.y, __ldg(&h[lane + 32]), acc1);
        }
    }

    // expmap0: |p| = tanh(un) analytically
    float un = fmaxf(sqrtf(wsum(acc0 * acc0 + acc1 * acc1)), 1e-15f);
    float tn = tanhf(un);
    float ps = tn / un;
    float pn = fmaxf(tn, 1e-15f);
    // relu(logmap0(p))
    float as = artanh_c(pn) / pn * ps;
    float xt0 = fmaxf(as * acc0, 0.f), xt1 = fmaxf(as * acc1, 0.f);
    // expmap0; |out| = tanh(xn)
    float xn = fmaxf(sqrtf(wsum(xt0 * xt0 + xt1 * xt1)), 1e-15f);
    float txn = tanhf(xn);
    float os = txn / xn;
    float o0 = os * xt0, o1 = os * xt1;
    // proj
    float on = fmaxf(txn, 1e-15f);
    float mxn = 1.0f - 1e-5f;
    if (on > mxn) { float f = mxn / on; o0 *= f; o1 *= f; }
    out[row * D + lane]      = o0;
    out[row * D + lane + 32] = o1;
}

// ---------------------------------------------------------------------------
extern "C" void kernel_launch(void* const* d_in, const int* in_sizes, int n_in,
                              void* d_out, int out_size)
{
    const float* x    = (const float*)d_in[0];
    const float* W    = (const float*)d_in[1];
    const float* ev   = (const float*)d_in[2];
    const int*   rows = (const int*)d_in[3];
    const int*   cols = (const int*)d_in[4];
    float* out = (float*)d_out;

    int N = in_sizes[0] / D;
    int E = in_sizes[2];

    int NA = (N + 63) / 64;           // A blocks (8 rows/warp * 8 warps)
    int NF = (E + 2047) / 2048;       // Fill blocks (8 edges/thread)
    kernelZ<<<(NMAX + 255) / 256, 256>>>();
    kernelAF<<<NA + NF, 256>>>(x, W, ev, rows, cols, N, E, NA);
    kernelSpmmC<<<(N + 7) / 8, 256>>>(out, N);
}

// round 10
// speedup vs baseline: 3.5368x; 1.0195x over previous
#include <cuda_runtime.h>
#include <cuda_fp16.h>

#define NMAX 100000
#define D 64
#define CAP 128            // per-row bucket capacity (Poisson(16): P(deg>=128) ~ 0)
#define FULL 0xffffffffu

typedef unsigned long long u64;

// Scratch (no device allocation).
__device__ __half g_hid[NMAX * D];            // 12.8 MB (fp16 hidden)
__device__ int    g_cnt[NMAX];
__device__ int2   g_edge[(size_t)NMAX * CAP]; // 102.4 MB: (col, val-bits)

__device__ __forceinline__ float wsum(float v) {
#pragma unroll
    for (int o = 16; o; o >>= 1) v += __shfl_xor_sync(FULL, v, o);
    return v;
}

// exact artanh with reference clipping (SpmmC epilogue, matching R9 winner)
__device__ __forceinline__ float artanh_c(float x) {
    return atanhf(fminf(x, 1.0f - 1e-7f));
}

// fast artanh for x in [0, 1): 0.5*ln((1+x)/(1-x)); ~1e-6 rel err (A epilogue)
__device__ __forceinline__ float artanh_f(float x) {
    x = fminf(x, 1.0f - 1e-7f);
    return 0.5f * __logf(__fdividef(1.0f + x, 1.0f - x));
}

__device__ __forceinline__ u64 ffma2(u64 a, u64 b, u64 c) {
    u64 d;
    asm("fma.rn.f32x2 %0, %1, %2, %3;" : "=l"(d) : "l"(a), "l"(b), "l"(c));
    return d;
}
__device__ __forceinline__ float2 unpack2(u64 v) {
    float2 r;
    asm("mov.b64 {%0, %1}, %2;" : "=f"(r.x), "=f"(r.y) : "l"(v));
    return r;
}
__device__ __forceinline__ u64 pack2(float lo, float hi) {
    u64 v;
    asm("mov.b64 %0, {%1, %2};" : "=l"(v) : "f"(lo), "f"(hi));
    return v;
}

// ---------------------------------------------------------------------------
// Kernel Z: zero the degree counters (runs before AF each call).
// ---------------------------------------------------------------------------
__global__ void __launch_bounds__(256) kernelZ()
{
    int i = blockIdx.x * 256 + threadIdx.x;
    if (i < NMAX) g_cnt[i] = 0;
}

// ---------------------------------------------------------------------------
// Kernel AF: blocks [0, NA) run fused linear+mobius+logmap0 (-> g_hid fp16);
//            blocks [NA, ...) bucket edges by destination row (g_edge/g_cnt).
// Disjoint state; Fill hides under A's compute.
// ---------------------------------------------------------------------------
__global__ void __launch_bounds__(256) kernelAF(
    const float* __restrict__ x, const float* __restrict__ W,
    const float* __restrict__ ev, const int* __restrict__ rows,
    const int* __restrict__ cols, int N, int E, int NA)
{
    if ((int)blockIdx.x >= NA) {
        // ---- Fill path: 8 edges per thread, independent (MLP=8) ----
        int e0 = (blockIdx.x - NA) * 2048 + threadIdx.x;
#pragma unroll
        for (int u = 0; u < 8; u++) {
            int e = e0 + u * 256;
            if (e < E) {
                int r = __ldg(&rows[e]);
                int pos = atomicAdd(&g_cnt[r], 1);
                if (pos < CAP)
                    g_edge[(size_t)r * CAP + pos] =
                        make_int2(__ldg(&cols[e]), __float_as_int(__ldg(&ev[e])));
            }
        }
        return;
    }

    // ---- A path: warp handles 8 rows as 4 packed row-pairs ----
    __shared__ float  Ws[D * 65];     // W^T, padded
    __shared__ float2 Xp[8][D][4];    // packed x row-pairs

    const int tid  = threadIdx.x;
    const int warp = tid >> 5;
    const int lane = tid & 31;

    for (int i = tid; i < D * D; i += 256) {
        int d = i >> 6, k = i & 63;
        Ws[k * 65 + d] = W[i];
    }

    const int base = (blockIdx.x * 8 + warp) * 8;
#pragma unroll
    for (int p = 0; p < 4; p++) {
        int r0 = base + 2 * p, r1 = r0 + 1;
        float a0 = (r0 < N) ? x[r0 * D + lane]      : 0.f;
        float a1 = (r0 < N) ? x[r0 * D + lane + 32] : 0.f;
        float b0 = (r1 < N) ? x[r1 * D + lane]      : 0.f;
        float b1 = (r1 < N) ? x[r1 * D + lane + 32] : 0.f;
        Xp[warp][lane][p]      = make_float2(a0, b0);
        Xp[warp][lane + 32][p] = make_float2(a1, b1);
    }
    __syncthreads();
    if (base >= N) return;

    u64 acc[4][2];
#pragma unroll
    for (int p = 0; p < 4; p++) { acc[p][0] = 0ull; acc[p][1] = 0ull; }

#pragma unroll 16
    for (int k = 0; k < D; k++) {
        float w0f = Ws[k * 65 + lane];
        float w1f = Ws[k * 65 + lane + 32];
        u64 w0 = pack2(w0f, w0f);
        u64 w1 = pack2(w1f, w1f);
        const u64* xr = reinterpret_cast<const u64*>(&Xp[warp][k][0]);
#pragma unroll
        for (int p = 0; p < 4; p++) {
            u64 xp = xr[p];
            acc[p][0] = ffma2(w0, xp, acc[p][0]);
            acc[p][1] = ffma2(w1, xp, acc[p][1]);
        }
    }

#pragma unroll
    for (int p = 0; p < 4; p++) {
        float2 c0 = unpack2(acc[p][0]);   // {mx[r0][lane],    mx[r1][lane]}
        float2 c1 = unpack2(acc[p][1]);   // {mx[r0][lane+32], mx[r1][lane+32]}
#pragma unroll
        for (int q = 0; q < 2; q++) {
            int row = base + 2 * p + q;
            if (row < N) {                 // uniform across warp
                float a0 = q ? c0.y : c0.x;
                float a1 = q ? c1.y : c1.x;
                float x0 = x[row * D + lane];        // L1 hits
                float x1 = x[row * D + lane + 32];
                float xn  = fmaxf(sqrtf(wsum(x0 * x0 + x1 * x1)), 1e-15f);
                float mxn = fmaxf(sqrtf(wsum(a0 * a0 + a1 * a1)), 1e-15f);
                unsigned bz = __ballot_sync(FULL, (a0 == 0.f) && (a1 == 0.f));
                float t = tanhf(__fdividef(mxn, xn) * artanh_f(xn));
                float scale = __fdividef(t, mxn);
                if (bz == FULL) scale = 0.f;
                // |res| = t analytically (res = mx*scale, scale >= 0)
                float pn = fmaxf(t, 1e-15f);
                float hs = __fdividef(artanh_f(pn), pn) * scale;
                g_hid[row * D + lane]      = __float2half_rn(a0 * hs);
                g_hid[row * D + lane + 32] = __float2half_rn(a1 * hs);
            }
        }
    }
}

// ---------------------------------------------------------------------------
// Fused SpMM (fp16 gather, fp32 accumulate) + expmap0 -> relu(logmap0)
// -> expmap0 -> proj => out.
// Loop structure IDENTICAL to the R9 winner (cooperative eb load + u64
// shuffle broadcast, unroll-4, no stores before the loop, exact epilogue);
// only the gather dtype changed: one __half2 per edge, lane owns feature
// pair (2*lane, 2*lane+1).
// ---------------------------------------------------------------------------
__global__ void __launch_bounds__(256) kernelSpmmC(float* __restrict__ out, int N)
{
    int row = blockIdx.x * 8 + (threadIdx.x >> 5);
    if (row >= N) return;
    int lane = threadIdx.x & 31;
    int deg = min(g_cnt[row], CAP);
    const int2* eb = &g_edge[(size_t)row * CAP];
    const __half2* hp = reinterpret_cast<const __half2*>(g_hid);

    float acc0 = 0.f, acc1 = 0.f;
    for (int s = 0; s < deg; s += 32) {
        int m = min(32, deg - s);
        u64 ep = 0ull;
        if (lane < m) {
            int2 er = __ldg(&eb[s + lane]);
            ep = pack2(__int_as_float(er.x), __int_as_float(er.y));
        }
        int j = 0;
        for (; j + 4 <= m; j += 4) {
#pragma unroll
            for (int u = 0; u < 4; u++) {
                u64 q = __shfl_sync(FULL, ep, j + u);
                float2 cv = unpack2(q);
                int c = __float_as_int(cv.x);
                float2 hf = __half22float2(__ldg(&hp[(size_t)c * 32 + lane]));
                acc0 = fmaf(cv.y, hf.x, acc0);
                acc1 = fmaf(cv.y, hf.y, acc1);
            }
        }
        for (; j < m; j++) {
            u64 q = __shfl_sync(FULL, ep, j);
            float2 cv = unpack2(q);
            int c = __float_as_int(cv.x);
            float2 hf = __half22float2(__ldg(&hp[(size_t)c * 32 + lane]));
            acc0 = fmaf(cv.y, hf.x, acc0);
            acc1 = fmaf(cv.y, hf.y, acc1);
        }
    }

    // expmap0: |p| = tanh(un) analytically
    float un = fmaxf(sqrtf(wsum(acc0 * acc0 + acc1 * acc1)), 1e-15f);
    float tn = tanhf(un);
    float ps = tn / un;
    float pn = fmaxf(tn, 1e-15f);
    // relu(logmap0(p))
    float as = artanh_c(pn) / pn * ps;
    float xt0 = fmaxf(as * acc0, 0.f), xt1 = fmaxf(as * acc1, 0.f);
    // expmap0; |out| = tanh(xn)
    float xn = fmaxf(sqrtf(wsum(xt0 * xt0 + xt1 * xt1)), 1e-15f);
    float txn = tanhf(xn);
    float os = txn / xn;
    float o0 = os * xt0, o1 = os * xt1;
    // proj
    float on = fmaxf(txn, 1e-15f);
    float mxn = 1.0f - 1e-5f;
    if (on > mxn) { float f = mxn / on; o0 *= f; o1 *= f; }
    reinterpret_cast<float2*>(out)[row * 32 + lane] = make_float2(o0, o1);
}

// ---------------------------------------------------------------------------
extern "C" void kernel_launch(void* const* d_in, const int* in_sizes, int n_in,
                              void* d_out, int out_size)
{
    const float* x    = (const float*)d_in[0];
    const float* W    = (const float*)d_in[1];
    const float* ev   = (const float*)d_in[2];
    const int*   rows = (const int*)d_in[3];
    const int*   cols = (const int*)d_in[4];
    float* out = (float*)d_out;

    int N = in_sizes[0] / D;
    int E = in_sizes[2];

    int NA = (N + 63) / 64;           // A blocks (8 rows/warp * 8 warps)
    int NF = (E + 2047) / 2048;       // Fill blocks (8 edges/thread)
    kernelZ<<<(NMAX + 255) / 256, 256>>>();
    kernelAF<<<NA + NF, 256>>>(x, W, ev, rows, cols, N, E, NA);
    kernelSpmmC<<<(N + 7) / 8, 256>>>(out, N);
}

// round 11
// speedup vs baseline: 3.5910x; 1.0153x over previous
#include <cuda_runtime.h>
#include <cuda_fp16.h>

#define NMAX 100000
#define D 64
#define CAP 128            // per-row bucket capacity (Poisson(16): P(deg>=128) ~ 0)
#define FULL 0xffffffffu

typedef unsigned long long u64;

// Scratch (no device allocation).
__device__ __half g_hid[NMAX * D];            // 12.8 MB (fp16 hidden)
__device__ int    g_cnt[NMAX];
__device__ int2   g_edge[(size_t)NMAX * CAP]; // 102.4 MB: (col, val-bits)

__device__ __forceinline__ float wsum(float v) {
#pragma unroll
    for (int o = 16; o; o >>= 1) v += __shfl_xor_sync(FULL, v, o);
    return v;
}

// fast sqrt (MUFU), inputs >= 0 here
__device__ __forceinline__ float sqrt_a(float x) {
    float r;
    asm("sqrt.approx.f32 %0, %1;" : "=f"(r) : "f"(x));
    return r;
}

// fast tanh for x >= 0: (1-e)/(1+e), e = exp(-2x); rel err ~1e-6
__device__ __forceinline__ float tanh_f(float x) {
    float e = __expf(-2.0f * x);
    return __fdividef(1.0f - e, 1.0f + e);
}

// fast artanh for x in [0, 1): 0.5*ln((1+x)/(1-x)); ~1e-6 rel err
__device__ __forceinline__ float artanh_f(float x) {
    x = fminf(x, 1.0f - 1e-7f);
    return 0.5f * __logf(__fdividef(1.0f + x, 1.0f - x));
}

__device__ __forceinline__ u64 ffma2(u64 a, u64 b, u64 c) {
    u64 d;
    asm("fma.rn.f32x2 %0, %1, %2, %3;" : "=l"(d) : "l"(a), "l"(b), "l"(c));
    return d;
}
__device__ __forceinline__ float2 unpack2(u64 v) {
    float2 r;
    asm("mov.b64 {%0, %1}, %2;" : "=f"(r.x), "=f"(r.y) : "l"(v));
    return r;
}
__device__ __forceinline__ u64 pack2(float lo, float hi) {
    u64 v;
    asm("mov.b64 %0, {%1, %2};" : "=l"(v) : "f"(lo), "f"(hi));
    return v;
}

// ---------------------------------------------------------------------------
// Kernel Z: zero the degree counters (runs before AF each call).
// ---------------------------------------------------------------------------
__global__ void __launch_bounds__(256) kernelZ()
{
    int i = blockIdx.x * 256 + threadIdx.x;
    if (i < NMAX) g_cnt[i] = 0;
}

// ---------------------------------------------------------------------------
// Kernel AF: blocks [0, NA) run fused linear+mobius+logmap0 (-> g_hid fp16);
//            blocks [NA, ...) bucket edges by destination row (g_edge/g_cnt).
// Disjoint state; Fill hides under A's compute.
// ---------------------------------------------------------------------------
__global__ void __launch_bounds__(256) kernelAF(
    const float* __restrict__ x, const float* __restrict__ W,
    const float* __restrict__ ev, const int* __restrict__ rows,
    const int* __restrict__ cols, int N, int E, int NA)
{
    if ((int)blockIdx.x >= NA) {
        // ---- Fill path: 8 edges per thread, independent (MLP=8) ----
        int e0 = (blockIdx.x - NA) * 2048 + threadIdx.x;
#pragma unroll
        for (int u = 0; u < 8; u++) {
            int e = e0 + u * 256;
            if (e < E) {
                int r = __ldg(&rows[e]);
                int pos = atomicAdd(&g_cnt[r], 1);
                if (pos < CAP)
                    g_edge[(size_t)r * CAP + pos] =
                        make_int2(__ldg(&cols[e]), __float_as_int(__ldg(&ev[e])));
            }
        }
        return;
    }

    // ---- A path: warp handles 8 rows as 4 packed row-pairs ----
    __shared__ float  Ws[D * 65];     // W^T, padded
    __shared__ float2 Xp[8][D][4];    // packed x row-pairs

    const int tid  = threadIdx.x;
    const int warp = tid >> 5;
    const int lane = tid & 31;

    for (int i = tid; i < D * D; i += 256) {
        int d = i >> 6, k = i & 63;
        Ws[k * 65 + d] = W[i];
    }

    const int base = (blockIdx.x * 8 + warp) * 8;
#pragma unroll
    for (int p = 0; p < 4; p++) {
        int r0 = base + 2 * p, r1 = r0 + 1;
        float a0 = (r0 < N) ? x[r0 * D + lane]      : 0.f;
        float a1 = (r0 < N) ? x[r0 * D + lane + 32] : 0.f;
        float b0 = (r1 < N) ? x[r1 * D + lane]      : 0.f;
        float b1 = (r1 < N) ? x[r1 * D + lane + 32] : 0.f;
        Xp[warp][lane][p]      = make_float2(a0, b0);
        Xp[warp][lane + 32][p] = make_float2(a1, b1);
    }
    __syncthreads();
    if (base >= N) return;

    u64 acc[4][2];
#pragma unroll
    for (int p = 0; p < 4; p++) { acc[p][0] = 0ull; acc[p][1] = 0ull; }

#pragma unroll 16
    for (int k = 0; k < D; k++) {
        float w0f = Ws[k * 65 + lane];
        float w1f = Ws[k * 65 + lane + 32];
        u64 w0 = pack2(w0f, w0f);
        u64 w1 = pack2(w1f, w1f);
        const u64* xr = reinterpret_cast<const u64*>(&Xp[warp][k][0]);
#pragma unroll
        for (int p = 0; p < 4; p++) {
            u64 xp = xr[p];
            acc[p][0] = ffma2(w0, xp, acc[p][0]);
            acc[p][1] = ffma2(w1, xp, acc[p][1]);
        }
    }

#pragma unroll
    for (int p = 0; p < 4; p++) {
        float2 c0 = unpack2(acc[p][0]);   // {mx[r0][lane],    mx[r1][lane]}
        float2 c1 = unpack2(acc[p][1]);   // {mx[r0][lane+32], mx[r1][lane+32]}
#pragma unroll
        for (int q = 0; q < 2; q++) {
            int row = base + 2 * p + q;
            if (row < N) {                 // uniform across warp
                float a0 = q ? c0.y : c0.x;
                float a1 = q ? c1.y : c1.x;
                float x0 = x[row * D + lane];        // L1 hits
                float x1 = x[row * D + lane + 32];
                float xn  = fmaxf(sqrt_a(wsum(x0 * x0 + x1 * x1)), 1e-15f);
                float mxn = fmaxf(sqrt_a(wsum(a0 * a0 + a1 * a1)), 1e-15f);
                // NOTE: the reference's "where(all(mx==0), 0, res)" is
                // numerically redundant: if mx == 0 then res = mx*scale = 0
                // and mxn is clamped, so no 0/0 occurs.
                float t = tanh_f(__fdividef(mxn, xn) * artanh_f(xn));
                float scale = __fdividef(t, mxn);
                // |res| = t analytically (res = mx*scale, scale >= 0)
                float pn = fmaxf(t, 1e-15f);
                float hs = __fdividef(artanh_f(pn), pn) * scale;
                g_hid[row * D + lane]      = __float2half_rn(a0 * hs);
                g_hid[row * D + lane + 32] = __float2half_rn(a1 * hs);
            }
        }
    }
}

// ---------------------------------------------------------------------------
// Fused SpMM (fp16 gather, fp32 accumulate) + expmap0 -> relu(logmap0)
// -> expmap0 -> proj => out.
// Gather loop byte-identical to the 116.6us winner (cooperative eb load +
// u64 shuffle broadcast, unroll-4, no stores before the loop); epilogue
// switched to fast math (exp-based tanh, approx sqrt, fast div, fast artanh).
// ---------------------------------------------------------------------------
__global__ void __launch_bounds__(256) kernelSpmmC(float* __restrict__ out, int N)
{
    int row = blockIdx.x * 8 + (threadIdx.x >> 5);
    if (row >= N) return;
    int lane = threadIdx.x & 31;
    int deg = min(g_cnt[row], CAP);
    const int2* eb = &g_edge[(size_t)row * CAP];
    const __half2* hp = reinterpret_cast<const __half2*>(g_hid);

    float acc0 = 0.f, acc1 = 0.f;
    for (int s = 0; s < deg; s += 32) {
        int m = min(32, deg - s);
        u64 ep = 0ull;
        if (lane < m) {
            int2 er = __ldg(&eb[s + lane]);
            ep = pack2(__int_as_float(er.x), __int_as_float(er.y));
        }
        int j = 0;
        for (; j + 4 <= m; j += 4) {
#pragma unroll
            for (int u = 0; u < 4; u++) {
                u64 q = __shfl_sync(FULL, ep, j + u);
                float2 cv = unpack2(q);
                int c = __float_as_int(cv.x);
                float2 hf = __half22float2(__ldg(&hp[(size_t)c * 32 + lane]));
                acc0 = fmaf(cv.y, hf.x, acc0);
                acc1 = fmaf(cv.y, hf.y, acc1);
            }
        }
        for (; j < m; j++) {
            u64 q = __shfl_sync(FULL, ep, j);
            float2 cv = unpack2(q);
            int c = __float_as_int(cv.x);
            float2 hf = __half22float2(__ldg(&hp[(size_t)c * 32 + lane]));
            acc0 = fmaf(cv.y, hf.x, acc0);
            acc1 = fmaf(cv.y, hf.y, acc1);
        }
    }

    // expmap0: |p| = tanh(un) analytically
    float un = fmaxf(sqrt_a(wsum(acc0 * acc0 + acc1 * acc1)), 1e-15f);
    float tn = tanh_f(un);
    float ps = __fdividef(tn, un);
    float pn = fmaxf(tn, 1e-15f);
    // relu(logmap0(p))
    float as = __fdividef(artanh_f(pn), pn) * ps;
    float xt0 = fmaxf(as * acc0, 0.f), xt1 = fmaxf(as * acc1, 0.f);
    // expmap0; |out| = tanh(xn) analytically
    float xn = fmaxf(sqrt_a(wsum(xt0 * xt0 + xt1 * xt1)), 1e-15f);
    float txn = tanh_f(xn);
    float os = __fdividef(txn, xn);
    float o0 = os * xt0, o1 = os * xt1;
    // proj
    float on = fmaxf(txn, 1e-15f);
    float mxn = 1.0f - 1e-5f;
    if (on > mxn) { float f = __fdividef(mxn, on); o0 *= f; o1 *= f; }
    reinterpret_cast<float2*>(out)[row * 32 + lane] = make_float2(o0, o1);
}

// ---------------------------------------------------------------------------
extern "C" void kernel_launch(void* const* d_in, const int* in_sizes, int n_in,
                              void* d_out, int out_size)
{
    const float* x    = (const float*)d_in[0];
    const float* W    = (const float*)d_in[1];
    const float* ev   = (const float*)d_in[2];
    const int*   rows = (const int*)d_in[3];
    const int*   cols = (const int*)d_in[4];
    float* out = (float*)d_out;

    int N = in_sizes[0] / D;
    int E = in_sizes[2];

    int NA = (N + 63) / 64;           // A blocks (8 rows/warp * 8 warps)
    int NF = (E + 2047) / 2048;       // Fill blocks (8 edges/thread)
    kernelZ<<<(NMAX + 255) / 256, 256>>>();
    kernelAF<<<NA + NF, 256>>>(x, W, ev, rows, cols, N, E, NA);
    kernelSpmmC<<<(N + 7) / 8, 256>>>(out, N);
}